// round 8
// baseline (speedup 1.0000x reference)
#include <cuda_runtime.h>
#include <math.h>

#define MAXLEN_  100
#define MAXB     65536
#define MAXROWS  501760            // >= N=500000, row capacity of xg scratch

// ---------------- scratch: xg[n][gate-pair p] as packed f32x2 (u64) ----------------
__device__ unsigned long long d_xg[(size_t)MAXROWS * 128];   // 514 MB

__device__ int d_start[MAXB];
__device__ int d_end[MAXB];
__device__ int d_is64;

// ---------------- packed dual-fp32 FMA (Blackwell FFMA2) ----------------
__device__ __forceinline__ unsigned long long ffma2(unsigned long long a,
                                                    unsigned long long b,
                                                    unsigned long long c) {
    unsigned long long d;
    asm("fma.rn.f32x2 %0, %1, %2, %3;" : "=l"(d) : "l"(a), "l"(b), "l"(c));
    return d;
}
__device__ __forceinline__ unsigned long long pack2(float lo, float hi) {
    unsigned long long d;
    asm("mov.b64 %0, {%1, %2};" : "=l"(d) : "f"(lo), "f"(hi));
    return d;
}

__device__ __forceinline__ float sigm_f(float v) { return 1.0f / (1.0f + __expf(-v)); }
__device__ __forceinline__ float tanh_f(float v) { return 1.0f - 2.0f / (__expf(2.0f * v) + 1.0f); }

// ---------------- launch 1: zero bounds + index dtype probe ----------------
__global__ void k_init_detect(const int* __restrict__ w32, int N, int B) {
    int i = blockIdx.x * blockDim.x + threadIdx.x;
    if (i < B) { d_start[i] = 0; d_end[i] = 0; }
    if (i == 0) d_is64 = (w32[N - 1] == 0) ? 1 : 0;   // int64 high word -> 0
}

// ---------------- launch 3: segment boundaries from sorted index ----------------
__global__ void k_bounds(const void* __restrict__ indexv, int N, int B) {
    int i = blockIdx.x * blockDim.x + threadIdx.x;
    if (i >= N) return;
    const int is64 = d_is64;
    int b, bp = -1, bn = -1;
    if (is64) {
        const long long* idx = (const long long*)indexv;
        b = (int)idx[i];
        if (i > 0) bp = (int)idx[i - 1];
        if (i < N - 1) bn = (int)idx[i + 1];
    } else {
        const int* idx = (const int*)indexv;
        b = idx[i];
        if (i > 0) bp = idx[i - 1];
        if (i < N - 1) bn = idx[i + 1];
    }
    if (b < 0 || b >= B) return;
    if (i == 0 || bp != b) d_start[b] = i;
    if (i == N - 1 || bn != b) d_end[b] = i + 1;
}

// =======================================================================
// launch 2: k_xgemm  xg[n][2p,2p+1] = x[n]·W_ih[2p,2p+1]^T + bias pair
// 256 threads, 32-row tiles, acc[16] u64 (32 regs -> no spills), FFMA2.
//  smem: sW pairs 64KB  [k2*128+p] = (wA_k0,wB_k0,wA_k1,wB_k1)
//        sX dup   16KB  [r*32+k2]  = (x_k0,x_k0,x_k1,x_k1)
// =======================================================================
#define XG_SMEM (65536 + 16384)

extern __shared__ unsigned char smem_raw[];

__global__ __launch_bounds__(256, 2)
void k_xgemm(const float* __restrict__ x,
             const float* __restrict__ W_ih,
             const float* __restrict__ b_ih,
             const float* __restrict__ b_hh,
             int N) {
    float4* sW = (float4*)smem_raw;                 // 4096 entries
    float4* sX = (float4*)(smem_raw + 65536);       // 1024 entries
    const ulonglong2* sWu = (const ulonglong2*)sW;
    const ulonglong2* sXu = (const ulonglong2*)sX;

    const int t = threadIdx.x;
    const int p = t & 127;      // gate pair
    const int half = t >> 7;    // rows 0..15 or 16..31

    for (int idx = t; idx < 4096; idx += 256) {
        int k2 = idx >> 7, pp = idx & 127;
        sW[idx] = make_float4(W_ih[(2 * pp)     * 64 + 2 * k2],
                              W_ih[(2 * pp + 1) * 64 + 2 * k2],
                              W_ih[(2 * pp)     * 64 + 2 * k2 + 1],
                              W_ih[(2 * pp + 1) * 64 + 2 * k2 + 1]);
    }
    const unsigned long long bias2 =
        pack2(b_ih[2 * p] + b_hh[2 * p], b_ih[2 * p + 1] + b_hh[2 * p + 1]);

    const int ntiles = (N + 31) >> 5;
    for (int tile = blockIdx.x; tile < ntiles; tile += gridDim.x) {
        const int row0 = tile << 5;
        __syncthreads();   // protect previous iteration's sX reads
        #pragma unroll
        for (int i = 0; i < 4; ++i) {
            int idx = t + i * 256;            // 0..1023
            int r = idx >> 5, k2 = idx & 31;
            int row = row0 + r;
            float2 v = make_float2(0.f, 0.f);
            if (row < N) v = ((const float2*)x)[(size_t)row * 32 + k2];
            sX[r * 32 + k2] = make_float4(v.x, v.x, v.y, v.y);
        }
        __syncthreads();

        unsigned long long acc[16];
        #pragma unroll
        for (int r = 0; r < 16; ++r) acc[r] = bias2;

        const int rbase = half * 16;
        #pragma unroll 4
        for (int k2 = 0; k2 < 32; ++k2) {
            ulonglong2 w = sWu[k2 * 128 + p];
            #pragma unroll
            for (int r = 0; r < 16; ++r) {
                ulonglong2 v = sXu[(rbase + r) * 32 + k2];   // warp-uniform -> broadcast
                acc[r] = ffma2(w.x, v.x, acc[r]);
                acc[r] = ffma2(w.y, v.y, acc[r]);
            }
        }

        #pragma unroll
        for (int r = 0; r < 16; ++r) {
            int row = row0 + rbase + r;
            if (row < N) d_xg[(size_t)row * 128 + p] = acc[r];
        }
    }
}

// =======================================================================
// launch 4: k_lstm — recurrence (K=64), gates seeded from d_xg.
// In-kernel deterministic length-ranking (block-redundant, no atomics):
//   rank(b) = offs[len(b)] + #{b' < b : len(b') == len(b)}   (descending len)
// Block i processes segments with ranks [8i, 8i+8).
//  smem (after ordering): sW pairs 64KB | sV dup-h 4KB | sG gates 8KB
//  ordering scratch aliases sW region (sLen <=32KB + sHist 26.6KB).
// =======================================================================
#define G        8
#define LT       128
#define L_SMEM   (65536 + 4096 + 8192)
#define ORD_MAXB 32768

__global__ __launch_bounds__(LT, 2)
void k_lstm(const float* __restrict__ W_hh,
            float* __restrict__ out,
            int B, int N) {
    float4* sW = (float4*)smem_raw;                       // 64KB
    float4* sV = (float4*)(smem_raw + 65536);             // 256 float4
    unsigned long long* sG = (unsigned long long*)(smem_raw + 65536 + 4096); // 1024 u64
    float2* sV2 = (float2*)sV;
    const ulonglong2* sWu = (const ulonglong2*)sW;
    const ulonglong2* sVu = (const ulonglong2*)sV;
    const float* gatesf = (const float*)sG;               // [seg][256]

    __shared__ int sOffs[MAXLEN_ + 3];
    __shared__ int sSeg[G];
    __shared__ int s_start[G], s_len[G], s_segid[G];

    const int t = threadIdx.x;
    const int win0 = blockIdx.x * G;

    if (t < G) sSeg[t] = -1;

    if (B <= ORD_MAXB) {
        // ---- deterministic descending-length ranking (scratch aliases sW) ----
        unsigned char*  sLen  = (unsigned char*)smem_raw;              // [<=32768]
        unsigned short* sHist = (unsigned short*)(smem_raw + ORD_MAXB);// [128][104]
        #pragma unroll
        for (int l = 0; l < 104; ++l) sHist[t * 104 + l] = 0;
        __syncthreads();

        const int chunk = (B + LT - 1) / LT;
        const int base = t * chunk;
        for (int j = 0; j < chunk; ++j) {
            int b = base + j;
            if (b >= B) break;
            int len = d_end[b] - d_start[b];
            len = min(max(len, 0), MAXLEN_);
            sLen[b] = (unsigned char)len;
            sHist[t * 104 + len]++;
        }
        __syncthreads();
        if (t <= MAXLEN_) {
            int run = 0;
            for (int tt = 0; tt < LT; ++tt) {
                int v = sHist[tt * 104 + t];
                sHist[tt * 104 + t] = (unsigned short)run;   // exclusive prefix over chunks
                run += v;
            }
            sOffs[t] = run;                                  // bin total
        }
        __syncthreads();
        if (t == 0) {
            int acc = 0;
            for (int l = MAXLEN_; l >= 0; --l) { int c = sOffs[l]; sOffs[l] = acc; acc += c; }
        }
        __syncthreads();
        for (int j = 0; j < chunk; ++j) {
            int b = base + j;
            if (b >= B) break;
            int l = sLen[b];
            int r = sOffs[l] + (int)sHist[t * 104 + l];
            sHist[t * 104 + l]++;
            int w = r - win0;
            if (w >= 0 && w < G) sSeg[w] = b;
        }
        __syncthreads();
        if (t < G) {
            int seg = sSeg[t];
            s_segid[t] = seg;
            if (seg >= 0) {
                int st = d_start[seg];
                int ln = sLen[seg];
                if (st < 0) st = 0;
                if (st > N) st = N;
                if (ln > N - st) ln = N - st;
                s_start[t] = st;
                s_len[t] = ln;
            } else { s_start[t] = 0; s_len[t] = 0; }
        }
    } else {
        // fallback: identity grouping
        if (t < G) {
            int seg = (win0 + t < B) ? (win0 + t) : -1;
            int st = (seg >= 0) ? d_start[seg] : 0;
            int ln = (seg >= 0) ? (d_end[seg] - d_start[seg]) : 0;
            ln = min(max(ln, 0), MAXLEN_);
            if (st < 0) st = 0;
            if (st > N) st = N;
            if (ln > N - st) ln = N - st;
            s_segid[t] = seg; s_start[t] = st; s_len[t] = ln;
        }
    }
    __syncthreads();   // metadata final; scratch free for weight staging

    // ---- stage W_hh pairs ----
    for (int idx = t; idx < 4096; idx += LT) {
        int k2 = idx >> 7, pp = idx & 127;
        sW[idx] = make_float4(W_hh[(2 * pp)     * 64 + 2 * k2],
                              W_hh[(2 * pp + 1) * 64 + 2 * k2],
                              W_hh[(2 * pp)     * 64 + 2 * k2 + 1],
                              W_hh[(2 * pp + 1) * 64 + 2 * k2 + 1]);
    }
    #pragma unroll
    for (int i = t; i < 256; i += LT) sV[i] = make_float4(0.f, 0.f, 0.f, 0.f);
    __syncthreads();

    int nsteps = 0;
    #pragma unroll
    for (int s = 0; s < G; ++s) nsteps = max(nsteps, s_len[s]);

    float hreg[4], creg[4];
    int segj[4], unitj[4];
    #pragma unroll
    for (int j = 0; j < 4; ++j) {
        int lin = t + LT * j;
        segj[j]  = lin >> 6;
        unitj[j] = lin & 63;
        hreg[j] = 0.f;
        creg[j] = 0.f;
    }

    unsigned long long cur[G];
    #pragma unroll
    for (int s = 0; s < G; ++s)
        cur[s] = (0 < s_len[s]) ? d_xg[(size_t)s_start[s] * 128 + t] : 0ull;

    for (int step = 0; step < nsteps; ++step) {
        unsigned long long nxt[G];
        #pragma unroll
        for (int s = 0; s < G; ++s) {
            int ns = step + 1;
            nxt[s] = (ns < s_len[s]) ? d_xg[(size_t)(s_start[s] + ns) * 128 + t] : 0ull;
        }

        // ---- gate-pair GEMV over h (K=64) for G segments ----
        unsigned long long acc[G];
        #pragma unroll
        for (int s = 0; s < G; ++s) acc[s] = cur[s];
        #pragma unroll 4
        for (int k2 = 0; k2 < 32; ++k2) {
            ulonglong2 w = sWu[k2 * 128 + t];
            #pragma unroll
            for (int s = 0; s < G; ++s) {
                ulonglong2 v = sVu[s * 32 + k2];   // warp-uniform -> broadcast
                acc[s] = ffma2(w.x, v.x, acc[s]);
                acc[s] = ffma2(w.y, v.y, acc[s]);
            }
        }
        #pragma unroll
        for (int s = 0; s < G; ++s) sG[s * 128 + t] = acc[s];
        __syncthreads();

        // ---- cell update (freeze finished segments) ----
        #pragma unroll
        for (int j = 0; j < 4; ++j) {
            int seg = segj[j], unit = unitj[j];
            if (step < s_len[seg]) {
                float gi = gatesf[seg * 256 + unit];
                float gf = gatesf[seg * 256 + 64 + unit];
                float gg = gatesf[seg * 256 + 128 + unit];
                float go = gatesf[seg * 256 + 192 + unit];
                float cn = sigm_f(gf) * creg[j] + sigm_f(gi) * tanh_f(gg);
                float hn = sigm_f(go) * tanh_f(cn);
                creg[j] = cn;
                hreg[j] = hn;
                sV2[seg * 64 + unit] = make_float2(hn, hn);
            }
        }
        __syncthreads();

        #pragma unroll
        for (int s = 0; s < G; ++s) cur[s] = nxt[s];
    }

    #pragma unroll
    for (int j = 0; j < 4; ++j) {
        int seg = segj[j];
        if (s_segid[seg] >= 0)
            out[(size_t)s_segid[seg] * 64 + unitj[j]] = hreg[j];
    }
}

extern "C" void kernel_launch(void* const* d_in, const int* in_sizes, int n_in,
                              void* d_out, int out_size) {
    const float* x    = (const float*)d_in[0];
    const float* W_ih = (const float*)d_in[1];
    const float* W_hh = (const float*)d_in[2];
    const float* b_ih = (const float*)d_in[3];
    const float* b_hh = (const float*)d_in[4];
    const void*  indexv = d_in[5];
    float* out = (float*)d_out;

    int N = in_sizes[0] / 64;
    int B = out_size / 64;
    if (B > MAXB) B = MAXB;
    if (N > MAXROWS) N = MAXROWS;

    cudaFuncSetAttribute(k_xgemm, cudaFuncAttributeMaxDynamicSharedMemorySize, XG_SMEM);
    cudaFuncSetAttribute(k_lstm,  cudaFuncAttributeMaxDynamicSharedMemorySize, L_SMEM);

    // exactly 4 launches; ncu capture slot (#4) = k_lstm
    k_init_detect<<<(B + 255) / 256, 256>>>((const int*)indexv, N, B);
    k_xgemm<<<296, 256, XG_SMEM>>>(x, W_ih, b_ih, b_hh, N);
    k_bounds<<<(N + 255) / 256, 256>>>(indexv, N, B);

    int nblk = (B + G - 1) / G;
    k_lstm<<<nblk, LT, L_SMEM>>>(W_hh, out, B, N);
}

// round 9
// speedup vs baseline: 1.1579x; 1.1579x over previous
#include <cuda_runtime.h>
#include <math.h>

#define MAXLEN_  100
#define MAXB     65536
#define MAXROWS  501760            // >= N=500000, row capacity of xg scratch

// ---------------- scratch: xg[n][gate-pair p] as packed f32x2 (u64) ----------------
__device__ unsigned long long d_xg[(size_t)MAXROWS * 128];   // 514 MB

__device__ int d_start[MAXB];
__device__ int d_end[MAXB];
__device__ int d_order[MAXB];
__device__ int d_is64;

// ---------------- packed dual-fp32 FMA (Blackwell FFMA2) ----------------
__device__ __forceinline__ unsigned long long ffma2(unsigned long long a,
                                                    unsigned long long b,
                                                    unsigned long long c) {
    unsigned long long d;
    asm("fma.rn.f32x2 %0, %1, %2, %3;" : "=l"(d) : "l"(a), "l"(b), "l"(c));
    return d;
}
__device__ __forceinline__ unsigned long long pack2(float lo, float hi) {
    unsigned long long d;
    asm("mov.b64 %0, {%1, %2};" : "=l"(d) : "f"(lo), "f"(hi));
    return d;
}

__device__ __forceinline__ float sigm_f(float v) { return 1.0f / (1.0f + __expf(-v)); }
__device__ __forceinline__ float tanh_f(float v) { return 1.0f - 2.0f / (__expf(2.0f * v) + 1.0f); }

// ---------------- launch 1: zero bounds + index dtype probe ----------------
__global__ void k_init_detect(const int* __restrict__ w32, int N, int B) {
    int i = blockIdx.x * blockDim.x + threadIdx.x;
    if (i < B) { d_start[i] = 0; d_end[i] = 0; }
    if (i == 0) d_is64 = (w32[N - 1] == 0) ? 1 : 0;   // int64 high word -> 0
}

// ---------------- launch 2: segment boundaries from sorted index ----------------
__global__ void k_bounds(const void* __restrict__ indexv, int N, int B) {
    int i = blockIdx.x * blockDim.x + threadIdx.x;
    if (i >= N) return;
    const int is64 = d_is64;
    int b, bp = -1, bn = -1;
    if (is64) {
        const long long* idx = (const long long*)indexv;
        b = (int)idx[i];
        if (i > 0) bp = (int)idx[i - 1];
        if (i < N - 1) bn = (int)idx[i + 1];
    } else {
        const int* idx = (const int*)indexv;
        b = idx[i];
        if (i > 0) bp = idx[i - 1];
        if (i < N - 1) bn = idx[i + 1];
    }
    if (b < 0 || b >= B) return;
    if (i == 0 || bp != b) d_start[b] = i;
    if (i == N - 1 || bn != b) d_end[b] = i + 1;
}

// ---------------- launch 3: descending-length counting sort -> d_order ----------
// Single block. Tie order is atomic-nondeterministic, but ties have EQUAL length
// so per-segment output is identical regardless -> deterministic results.
__global__ void k_rank(int B, int N) {
    __shared__ int hist[MAXLEN_ + 1];
    __shared__ int offs[MAXLEN_ + 1];
    __shared__ int curs[MAXLEN_ + 1];
    const int t = threadIdx.x;
    for (int l = t; l <= MAXLEN_; l += blockDim.x) { hist[l] = 0; curs[l] = 0; }
    __syncthreads();
    for (int b = t; b < B; b += blockDim.x) {
        int l = d_end[b] - d_start[b];
        l = min(max(l, 0), MAXLEN_);
        atomicAdd(&hist[l], 1);
    }
    __syncthreads();
    if (t == 0) {
        int acc = 0;
        for (int l = MAXLEN_; l >= 0; --l) { offs[l] = acc; acc += hist[l]; }
    }
    __syncthreads();
    for (int b = t; b < B; b += blockDim.x) {
        int l = d_end[b] - d_start[b];
        l = min(max(l, 0), MAXLEN_);
        int p = offs[l] + atomicAdd(&curs[l], 1);
        d_order[p] = b;     // p in [0, B)
    }
}

// =======================================================================
// launch 4 (ncu capture slot): k_xgemm
//   xg[n][2p,2p+1] = x[n]·W_ih[2p,2p+1]^T + bias pair       (R6 shape)
// 256 threads, 64-row tiles, acc[32] u64, FFMA2.
//  smem: sW pairs 64KB [k2*128+p] = (wA_k0,wB_k0,wA_k1,wB_k1)
//        sX dup   32KB [r*32+k2]  = (x_k0,x_k0,x_k1,x_k1)
// =======================================================================
#define XG_SMEM (65536 + 32768)

extern __shared__ unsigned char smem_raw[];

__global__ __launch_bounds__(256, 2)
void k_xgemm(const float* __restrict__ x,
             const float* __restrict__ W_ih,
             const float* __restrict__ b_ih,
             const float* __restrict__ b_hh,
             int N) {
    float4* sW = (float4*)smem_raw;                 // 4096 entries
    float4* sX = (float4*)(smem_raw + 65536);       // 2048 entries
    const ulonglong2* sWu = (const ulonglong2*)sW;
    const ulonglong2* sXu = (const ulonglong2*)sX;

    const int t = threadIdx.x;
    const int p = t & 127;      // gate pair
    const int half = t >> 7;    // rows 0..31 or 32..63

    for (int idx = t; idx < 4096; idx += 256) {
        int k2 = idx >> 7, pp = idx & 127;
        sW[idx] = make_float4(W_ih[(2 * pp)     * 64 + 2 * k2],
                              W_ih[(2 * pp + 1) * 64 + 2 * k2],
                              W_ih[(2 * pp)     * 64 + 2 * k2 + 1],
                              W_ih[(2 * pp + 1) * 64 + 2 * k2 + 1]);
    }
    const unsigned long long bias2 =
        pack2(b_ih[2 * p] + b_hh[2 * p], b_ih[2 * p + 1] + b_hh[2 * p + 1]);

    const int ntiles = (N + 63) >> 6;
    for (int tile = blockIdx.x; tile < ntiles; tile += gridDim.x) {
        const int row0 = tile << 6;
        __syncthreads();   // protect previous iteration's sX reads
        #pragma unroll
        for (int i = 0; i < 8; ++i) {
            int idx = t + i * 256;            // 0..2047
            int r = idx >> 5, k2 = idx & 31;
            int row = row0 + r;
            float2 v = make_float2(0.f, 0.f);
            if (row < N) v = ((const float2*)x)[(size_t)row * 32 + k2];
            sX[r * 32 + k2] = make_float4(v.x, v.x, v.y, v.y);
        }
        __syncthreads();

        unsigned long long acc[32];
        #pragma unroll
        for (int r = 0; r < 32; ++r) acc[r] = bias2;

        const int rbase = half * 32;
        for (int k2 = 0; k2 < 32; ++k2) {
            ulonglong2 w = sWu[k2 * 128 + p];
            #pragma unroll
            for (int r = 0; r < 32; ++r) {
                ulonglong2 v = sXu[(rbase + r) * 32 + k2];   // warp-uniform -> broadcast
                acc[r] = ffma2(w.x, v.x, acc[r]);
                acc[r] = ffma2(w.y, v.y, acc[r]);
            }
        }

        #pragma unroll
        for (int r = 0; r < 32; ++r) {
            int row = row0 + rbase + r;
            if (row < N) d_xg[(size_t)row * 128 + p] = acc[r];
        }
    }
}

// =======================================================================
// launch 5: k_lstm — recurrence (K=64), gates seeded from d_xg.
// G=16 segments per block (halves total block-steps vs G=8), 128 threads,
// 2 blocks/SM.  smem: sW pairs 64KB | sV dup-h 8KB | sG gates 16KB = 88KB.
// =======================================================================
#define G        16
#define LT       128
#define L_SMEM   (65536 + 8192 + 16384)

__global__ __launch_bounds__(LT, 2)
void k_lstm(const float* __restrict__ W_hh,
            float* __restrict__ out,
            int B, int N) {
    float4* sW = (float4*)smem_raw;                       // 64KB
    float4* sV = (float4*)(smem_raw + 65536);             // 512 float4 = 8KB
    unsigned long long* sG = (unsigned long long*)(smem_raw + 65536 + 8192); // 2048 u64
    float2* sV2 = (float2*)sV;                            // sV2[seg*64+unit]=(h,h)
    const ulonglong2* sWu = (const ulonglong2*)sW;
    const ulonglong2* sVu = (const ulonglong2*)sV;
    const float* gatesf = (const float*)sG;               // [seg][256]
    __shared__ int s_start[G], s_len[G], s_segid[G];

    const int t = threadIdx.x;    // == gate pair p

    // ---- stage W_hh pairs ----
    for (int idx = t; idx < 4096; idx += LT) {
        int k2 = idx >> 7, pp = idx & 127;
        sW[idx] = make_float4(W_hh[(2 * pp)     * 64 + 2 * k2],
                              W_hh[(2 * pp + 1) * 64 + 2 * k2],
                              W_hh[(2 * pp)     * 64 + 2 * k2 + 1],
                              W_hh[(2 * pp + 1) * 64 + 2 * k2 + 1]);
    }
    // ---- segment metadata from precomputed order ----
    if (t < G) {
        int gi  = blockIdx.x * G + t;
        int seg = (gi < B) ? d_order[gi] : -1;
        int st  = (seg >= 0) ? d_start[seg] : 0;
        int en  = (seg >= 0) ? d_end[seg] : 0;
        int ln  = en - st;
        ln = min(max(ln, 0), MAXLEN_);
        if (st < 0) st = 0;
        if (st > N) st = N;
        if (ln > N - st) ln = N - st;
        s_segid[t] = seg;
        s_start[t] = st;
        s_len[t]   = ln;
    }
    for (int i = t; i < G * 32; i += LT) sV[i] = make_float4(0.f, 0.f, 0.f, 0.f);
    __syncthreads();

    int nsteps = 0;
    #pragma unroll
    for (int s = 0; s < G; ++s) nsteps = max(nsteps, s_len[s]);

    // per-thread cell slots: lin = t + 128*j -> (seg, unit), j = 0..7
    float hreg[8], creg[8];
    #pragma unroll
    for (int j = 0; j < 8; ++j) { hreg[j] = 0.f; creg[j] = 0.f; }

    // xg for step 0
    unsigned long long cur[G];
    #pragma unroll
    for (int s = 0; s < G; ++s)
        cur[s] = (0 < s_len[s]) ? d_xg[(size_t)s_start[s] * 128 + t] : 0ull;

    for (int step = 0; step < nsteps; ++step) {
        // consume cur into acc, then prefetch next step into cur (hidden under GEMV)
        unsigned long long acc[G];
        #pragma unroll
        for (int s = 0; s < G; ++s) acc[s] = cur[s];
        #pragma unroll
        for (int s = 0; s < G; ++s) {
            int ns = step + 1;
            cur[s] = (ns < s_len[s]) ? d_xg[(size_t)(s_start[s] + ns) * 128 + t] : 0ull;
        }

        // ---- gate-pair GEMV over h (K=64) for G segments ----
        #pragma unroll 2
        for (int k2 = 0; k2 < 32; ++k2) {
            ulonglong2 w = sWu[k2 * 128 + t];
            #pragma unroll
            for (int s = 0; s < G; ++s) {
                ulonglong2 v = sVu[s * 32 + k2];   // warp-uniform -> broadcast
                acc[s] = ffma2(w.x, v.x, acc[s]);
                acc[s] = ffma2(w.y, v.y, acc[s]);
            }
        }
        #pragma unroll
        for (int s = 0; s < G; ++s) sG[s * 128 + t] = acc[s];
        __syncthreads();

        // ---- cell update (freeze finished segments) ----
        #pragma unroll
        for (int j = 0; j < 8; ++j) {
            int lin = t + LT * j;
            int seg = lin >> 6, unit = lin & 63;
            if (step < s_len[seg]) {
                float gi = gatesf[seg * 256 + unit];
                float gf = gatesf[seg * 256 + 64 + unit];
                float gg = gatesf[seg * 256 + 128 + unit];
                float go = gatesf[seg * 256 + 192 + unit];
                float cn = sigm_f(gf) * creg[j] + sigm_f(gi) * tanh_f(gg);
                float hn = sigm_f(go) * tanh_f(cn);
                creg[j] = cn;
                hreg[j] = hn;
                sV2[seg * 64 + unit] = make_float2(hn, hn);
            }
        }
        __syncthreads();
    }

    // ---- emit last hidden (zero-length segments emit 0) ----
    #pragma unroll
    for (int j = 0; j < 8; ++j) {
        int lin = t + LT * j;
        int seg = lin >> 6, unit = lin & 63;
        if (s_segid[seg] >= 0)
            out[(size_t)s_segid[seg] * 64 + unit] = hreg[j];
    }
}

extern "C" void kernel_launch(void* const* d_in, const int* in_sizes, int n_in,
                              void* d_out, int out_size) {
    const float* x    = (const float*)d_in[0];
    const float* W_ih = (const float*)d_in[1];
    const float* W_hh = (const float*)d_in[2];
    const float* b_ih = (const float*)d_in[3];
    const float* b_hh = (const float*)d_in[4];
    const void*  indexv = d_in[5];
    float* out = (float*)d_out;

    int N = in_sizes[0] / 64;
    int B = out_size / 64;
    if (B > MAXB) B = MAXB;
    if (N > MAXROWS) N = MAXROWS;

    cudaFuncSetAttribute(k_xgemm, cudaFuncAttributeMaxDynamicSharedMemorySize, XG_SMEM);
    cudaFuncSetAttribute(k_lstm,  cudaFuncAttributeMaxDynamicSharedMemorySize, L_SMEM);

    // 5 launches; ncu capture slot (#4) = k_xgemm
    k_init_detect<<<(B + 255) / 256, 256>>>((const int*)indexv, N, B);
    k_bounds<<<(N + 255) / 256, 256>>>(indexv, N, B);
    k_rank<<<1, 1024>>>(B, N);
    k_xgemm<<<296, 256, XG_SMEM>>>(x, W_ih, b_ih, b_hh, N);

    int nblk = (B + G - 1) / G;
    k_lstm<<<nblk, LT, L_SMEM>>>(W_hh, out, B, N);
}

// round 10
// speedup vs baseline: 1.3297x; 1.1484x over previous
#include <cuda_runtime.h>
#include <math.h>

#define MAXLEN_  100
#define MAXB     65536
#define MAXROWS  501760            // >= N=500000, row capacity of xg scratch

// ---------------- scratch: xg[n][gate-pair p] as packed f32x2 (u64) ----------------
__device__ unsigned long long d_xg[(size_t)MAXROWS * 128];   // 514 MB

__device__ int d_start[MAXB];
__device__ int d_end[MAXB];
__device__ int d_order[MAXB];
__device__ int d_is64;

// ---------------- packed dual-fp32 FMA (Blackwell FFMA2) ----------------
__device__ __forceinline__ unsigned long long ffma2(unsigned long long a,
                                                    unsigned long long b,
                                                    unsigned long long c) {
    unsigned long long d;
    asm("fma.rn.f32x2 %0, %1, %2, %3;" : "=l"(d) : "l"(a), "l"(b), "l"(c));
    return d;
}
__device__ __forceinline__ unsigned long long pack2(float lo, float hi) {
    unsigned long long d;
    asm("mov.b64 %0, {%1, %2};" : "=l"(d) : "f"(lo), "f"(hi));
    return d;
}

__device__ __forceinline__ float sigm_f(float v) { return 1.0f / (1.0f + __expf(-v)); }
__device__ __forceinline__ float tanh_f(float v) { return 1.0f - 2.0f / (__expf(2.0f * v) + 1.0f); }

// ---------------- launch 1: zero bounds + index dtype probe ----------------
__global__ void k_init_detect(const int* __restrict__ w32, int N, int B) {
    int i = blockIdx.x * blockDim.x + threadIdx.x;
    if (i < B) { d_start[i] = 0; d_end[i] = 0; }
    if (i == 0) d_is64 = (w32[N - 1] == 0) ? 1 : 0;   // int64 high word -> 0
}

// ---------------- launch 2: segment boundaries from sorted index ----------------
__global__ void k_bounds(const void* __restrict__ indexv, int N, int B) {
    int i = blockIdx.x * blockDim.x + threadIdx.x;
    if (i >= N) return;
    const int is64 = d_is64;
    int b, bp = -1, bn = -1;
    if (is64) {
        const long long* idx = (const long long*)indexv;
        b = (int)idx[i];
        if (i > 0) bp = (int)idx[i - 1];
        if (i < N - 1) bn = (int)idx[i + 1];
    } else {
        const int* idx = (const int*)indexv;
        b = idx[i];
        if (i > 0) bp = idx[i - 1];
        if (i < N - 1) bn = idx[i + 1];
    }
    if (b < 0 || b >= B) return;
    if (i == 0 || bp != b) d_start[b] = i;
    if (i == N - 1 || bn != b) d_end[b] = i + 1;
}

// =======================================================================
// launch 3: k_xgemm_rank
//  Block 0 prologue: descending-length counting sort -> d_order (tiny).
//  All blocks:  xg[n][4q..4q+3] = x[n]·W_ih^T + bias  (2 gate-pairs/thread)
//  256 threads = (q = t&63: pairs 2q,2q+1) x (rh = t>>6: 16-row quarter),
//  64-row tiles. Per k2: 2 w-LDS + 16 v-LDS per 64 FFMA2 (was 33 per 64).
//  smem: sWa 32KB | sWb 32KB | sX dup 32KB = 96KB (2 blocks/SM)
// =======================================================================
#define XG_SMEM (32768 + 32768 + 32768)

extern __shared__ unsigned char smem_raw[];

__global__ __launch_bounds__(256, 2)
void k_xgemm_rank(const float* __restrict__ x,
                  const float* __restrict__ W_ih,
                  const float* __restrict__ b_ih,
                  const float* __restrict__ b_hh,
                  int N, int B) {
    // ---- block 0: rank segments by descending length (ties: any order, equal len) ----
    if (blockIdx.x == 0) {
        __shared__ int hist[MAXLEN_ + 1], offs[MAXLEN_ + 1], curs[MAXLEN_ + 1];
        const int tt = threadIdx.x;
        for (int l = tt; l <= MAXLEN_; l += 256) { hist[l] = 0; curs[l] = 0; }
        __syncthreads();
        for (int b = tt; b < B; b += 256) {
            int l = d_end[b] - d_start[b];
            l = min(max(l, 0), MAXLEN_);
            atomicAdd(&hist[l], 1);
        }
        __syncthreads();
        if (tt == 0) {
            int acc = 0;
            for (int l = MAXLEN_; l >= 0; --l) { offs[l] = acc; acc += hist[l]; }
        }
        __syncthreads();
        for (int b = tt; b < B; b += 256) {
            int l = d_end[b] - d_start[b];
            l = min(max(l, 0), MAXLEN_);
            int p = offs[l] + atomicAdd(&curs[l], 1);
            d_order[p] = b;
        }
        // no extra sync needed: gemm below uses dynamic smem only, tile loop syncs
    }

    float4* sWa = (float4*)smem_raw;                    // [k2*64+q] pairs 2q   (gates 4q,4q+1)
    float4* sWb = (float4*)(smem_raw + 32768);          // [k2*64+q] pairs 2q+1 (gates 4q+2,4q+3)
    float4* sX  = (float4*)(smem_raw + 65536);          // [r*32+k2] = (x_k0,x_k0,x_k1,x_k1)
    const ulonglong2* sWau = (const ulonglong2*)sWa;
    const ulonglong2* sWbu = (const ulonglong2*)sWb;
    const ulonglong2* sXu  = (const ulonglong2*)sX;

    const int t = threadIdx.x;
    const int q  = t & 63;      // pair-group: owns gate pairs 2q, 2q+1
    const int rh = t >> 6;      // row quarter: rows rh*16 .. rh*16+15

    // stage weights: entry [k2*64+q] = (w[g][2k2], w[g+1][2k2], w[g][2k2+1], w[g+1][2k2+1])
    for (int idx = t; idx < 2048; idx += 256) {
        int k2 = idx >> 6, qq = idx & 63;
        int ga = 4 * qq;          // sWa gates
        sWa[idx] = make_float4(W_ih[ga * 64 + 2 * k2],       W_ih[(ga + 1) * 64 + 2 * k2],
                               W_ih[ga * 64 + 2 * k2 + 1],   W_ih[(ga + 1) * 64 + 2 * k2 + 1]);
        int gb = 4 * qq + 2;      // sWb gates
        sWb[idx] = make_float4(W_ih[gb * 64 + 2 * k2],       W_ih[(gb + 1) * 64 + 2 * k2],
                               W_ih[gb * 64 + 2 * k2 + 1],   W_ih[(gb + 1) * 64 + 2 * k2 + 1]);
    }
    const unsigned long long bias0 =
        pack2(b_ih[4 * q] + b_hh[4 * q],         b_ih[4 * q + 1] + b_hh[4 * q + 1]);
    const unsigned long long bias1 =
        pack2(b_ih[4 * q + 2] + b_hh[4 * q + 2], b_ih[4 * q + 3] + b_hh[4 * q + 3]);

    const int ntiles = (N + 63) >> 6;
    for (int tile = blockIdx.x; tile < ntiles; tile += gridDim.x) {
        const int row0 = tile << 6;
        __syncthreads();   // protect previous iteration's sX reads
        #pragma unroll
        for (int i = 0; i < 8; ++i) {
            int idx = t + i * 256;            // 0..2047
            int r = idx >> 5, k2 = idx & 31;
            int row = row0 + r;
            float2 v = make_float2(0.f, 0.f);
            if (row < N) v = ((const float2*)x)[(size_t)row * 32 + k2];
            sX[r * 32 + k2] = make_float4(v.x, v.x, v.y, v.y);
        }
        __syncthreads();

        unsigned long long acc0[16], acc1[16];
        #pragma unroll
        for (int r = 0; r < 16; ++r) { acc0[r] = bias0; acc1[r] = bias1; }

        const int rbase = rh * 16;
        for (int k2 = 0; k2 < 32; ++k2) {
            ulonglong2 wa = sWau[k2 * 64 + q];
            ulonglong2 wb = sWbu[k2 * 64 + q];
            #pragma unroll
            for (int r = 0; r < 16; ++r) {
                ulonglong2 v = sXu[(rbase + r) * 32 + k2];   // warp-uniform -> broadcast
                acc0[r] = ffma2(wa.x, v.x, acc0[r]);
                acc0[r] = ffma2(wa.y, v.y, acc0[r]);
                acc1[r] = ffma2(wb.x, v.x, acc1[r]);
                acc1[r] = ffma2(wb.y, v.y, acc1[r]);
            }
        }

        #pragma unroll
        for (int r = 0; r < 16; ++r) {
            int row = row0 + rbase + r;
            if (row < N) {
                ulonglong2 o; o.x = acc0[r]; o.y = acc1[r];
                *(ulonglong2*)&d_xg[(size_t)row * 128 + 2 * q] = o;   // STG.128
            }
        }
    }
}

// =======================================================================
// launch 4 (ncu capture slot): k_lstm — recurrence (K=64), gates from d_xg.
// 256 threads = (p = t&127: gate pair) x (half = t>>7: 8-segment group).
// G=16 segments/block, 2 blocks/SM. Per-thread state: cur[8]+acc[8] -> no spill.
//  smem: sW pairs 64KB | sV dup-h 8KB | sG gates 16KB = 88KB
// =======================================================================
#define G        16
#define LT       256
#define L_SMEM   (65536 + 8192 + 16384)

__global__ __launch_bounds__(LT, 2)
void k_lstm(const float* __restrict__ W_hh,
            float* __restrict__ out,
            int B, int N) {
    float4* sW = (float4*)smem_raw;                       // [k2*128+p], 64KB
    float4* sV = (float4*)(smem_raw + 65536);             // 512 float4 = 8KB
    unsigned long long* sG = (unsigned long long*)(smem_raw + 65536 + 8192); // 2048 u64
    float2* sV2 = (float2*)sV;                            // sV2[seg*64+unit]=(h,h)
    const ulonglong2* sWu = (const ulonglong2*)sW;
    const ulonglong2* sVu = (const ulonglong2*)sV;
    const float* gatesf = (const float*)sG;               // [seg][256]
    __shared__ int s_start[G], s_len[G], s_segid[G];

    const int t = threadIdx.x;
    const int p    = t & 127;   // gate pair
    const int half = t >> 7;    // segment group: s0..s0+7
    const int s0   = half * 8;

    // ---- stage W_hh pairs ----
    for (int idx = t; idx < 4096; idx += LT) {
        int k2 = idx >> 7, pp = idx & 127;
        sW[idx] = make_float4(W_hh[(2 * pp)     * 64 + 2 * k2],
                              W_hh[(2 * pp + 1) * 64 + 2 * k2],
                              W_hh[(2 * pp)     * 64 + 2 * k2 + 1],
                              W_hh[(2 * pp + 1) * 64 + 2 * k2 + 1]);
    }
    // ---- segment metadata from precomputed order ----
    if (t < G) {
        int gi  = blockIdx.x * G + t;
        int seg = (gi < B) ? d_order[gi] : -1;
        int st  = (seg >= 0) ? d_start[seg] : 0;
        int en  = (seg >= 0) ? d_end[seg] : 0;
        int ln  = en - st;
        ln = min(max(ln, 0), MAXLEN_);
        if (st < 0) st = 0;
        if (st > N) st = N;
        if (ln > N - st) ln = N - st;
        s_segid[t] = seg;
        s_start[t] = st;
        s_len[t]   = ln;
    }
    for (int i = t; i < G * 32; i += LT) sV[i] = make_float4(0.f, 0.f, 0.f, 0.f);
    __syncthreads();

    int nsteps = 0;
    #pragma unroll
    for (int s = 0; s < G; ++s) nsteps = max(nsteps, s_len[s]);

    // per-thread cell slots: lin = t + 256*j -> (seg, unit), j = 0..3
    float hreg[4], creg[4];
    #pragma unroll
    for (int j = 0; j < 4; ++j) { hreg[j] = 0.f; creg[j] = 0.f; }

    // xg for step 0 (this thread's 8 segments)
    unsigned long long cur[8];
    #pragma unroll
    for (int s = 0; s < 8; ++s)
        cur[s] = (0 < s_len[s0 + s]) ? d_xg[(size_t)s_start[s0 + s] * 128 + p] : 0ull;

    for (int step = 0; step < nsteps; ++step) {
        // consume cur into acc, then prefetch next step into cur (hidden under GEMV)
        unsigned long long acc[8];
        #pragma unroll
        for (int s = 0; s < 8; ++s) acc[s] = cur[s];
        #pragma unroll
        for (int s = 0; s < 8; ++s) {
            int ns = step + 1;
            cur[s] = (ns < s_len[s0 + s]) ? d_xg[(size_t)(s_start[s0 + s] + ns) * 128 + p] : 0ull;
        }

        // ---- gate-pair GEMV over h (K=64) for this thread's 8 segments ----
        #pragma unroll 4
        for (int k2 = 0; k2 < 32; ++k2) {
            ulonglong2 w = sWu[k2 * 128 + p];
            #pragma unroll
            for (int s = 0; s < 8; ++s) {
                ulonglong2 v = sVu[(s0 + s) * 32 + k2];   // warp-uniform -> broadcast
                acc[s] = ffma2(w.x, v.x, acc[s]);
                acc[s] = ffma2(w.y, v.y, acc[s]);
            }
        }
        #pragma unroll
        for (int s = 0; s < 8; ++s) sG[(s0 + s) * 128 + p] = acc[s];
        __syncthreads();

        // ---- cell update (freeze finished segments) ----
        #pragma unroll
        for (int j = 0; j < 4; ++j) {
            int lin = t + LT * j;
            int seg = lin >> 6, unit = lin & 63;
            if (step < s_len[seg]) {
                float gi = gatesf[seg * 256 + unit];
                float gf = gatesf[seg * 256 + 64 + unit];
                float gg = gatesf[seg * 256 + 128 + unit];
                float go = gatesf[seg * 256 + 192 + unit];
                float cn = sigm_f(gf) * creg[j] + sigm_f(gi) * tanh_f(gg);
                float hn = sigm_f(go) * tanh_f(cn);
                creg[j] = cn;
                hreg[j] = hn;
                sV2[seg * 64 + unit] = make_float2(hn, hn);
            }
        }
        __syncthreads();
    }

    // ---- emit last hidden (zero-length segments emit 0) ----
    #pragma unroll
    for (int j = 0; j < 4; ++j) {
        int lin = t + LT * j;
        int seg = lin >> 6, unit = lin & 63;
        if (s_segid[seg] >= 0)
            out[(size_t)s_segid[seg] * 64 + unit] = hreg[j];
    }
}

extern "C" void kernel_launch(void* const* d_in, const int* in_sizes, int n_in,
                              void* d_out, int out_size) {
    const float* x    = (const float*)d_in[0];
    const float* W_ih = (const float*)d_in[1];
    const float* W_hh = (const float*)d_in[2];
    const float* b_ih = (const float*)d_in[3];
    const float* b_hh = (const float*)d_in[4];
    const void*  indexv = d_in[5];
    float* out = (float*)d_out;

    int N = in_sizes[0] / 64;
    int B = out_size / 64;
    if (B > MAXB) B = MAXB;
    if (N > MAXROWS) N = MAXROWS;

    cudaFuncSetAttribute(k_xgemm_rank, cudaFuncAttributeMaxDynamicSharedMemorySize, XG_SMEM);
    cudaFuncSetAttribute(k_lstm,       cudaFuncAttributeMaxDynamicSharedMemorySize, L_SMEM);

    // exactly 4 launches; ncu capture slot (#4) = k_lstm
    k_init_detect<<<(B + 255) / 256, 256>>>((const int*)indexv, N, B);
    k_bounds<<<(N + 255) / 256, 256>>>(indexv, N, B);
    k_xgemm_rank<<<296, 256, XG_SMEM>>>(x, W_ih, b_ih, b_hh, N, B);

    int nblk = (B + G - 1) / G;
    k_lstm<<<nblk, LT, L_SMEM>>>(W_hh, out, B, N);
}